// round 17
// baseline (speedup 1.0000x reference)
#include <cuda_runtime.h>
#include <cuda_fp16.h>
#include <cuda.h>
#include <cstdint>

// ---------------- problem shapes ----------------
#define BB 32
#define AA 32
#define SSQ 128
#define DD 1024
#define NHQ 1024                   // N*H
#define COLS2 2048                 // Q cols + K cols
#define ROWS 1024                  // B*A
#define ENC_ROW_STRIDE ((size_t)SSQ * DD)

#define LO_SCALE 256.0f
#define LO_INV   (1.0f / 256.0f)

// ---------------- device scratch (no allocs allowed) ----------------
__device__ __half g_A2[2][ROWS * DD];     // [hi/lo][row][k]   (CLS splits, lo *256)
__device__ __half g_B2[2][COLS2 * DD];    // [hi/lo][col][k]   (W^T splits, lo *256)
__device__ float g_lpart[16 * ROWS];      // [colTile][row] partial logits

// ---------------- split helper ----------------
__device__ __forceinline__ void split2(float x, __half& h, __half& l) {
    h = __float2half_rn(x);
    float r = x - __half2float(h);
    l = __float2half_rn(r * LO_SCALE);
}

// ---------------- kernel 1: fused splits (CLS + W) ----------------
// blocks [0, ROWS): CLS rows. blocks [ROWS, ROWS+1024): W 64d x 32n transpose tiles.
__global__ void __launch_bounds__(256, 1)
split_all_kernel(const float* __restrict__ enc,
                 const float* __restrict__ wq, const float* __restrict__ wk)
{
    int bx = blockIdx.x;
    int tid = threadIdx.x;
    if (bx < ROWS) {
        // ---- CLS rows -> 2 fp16 planes ----
        int r = bx;
        float4 v = reinterpret_cast<const float4*>(enc + (size_t)r * ENC_ROW_STRIDE)[tid];
        float xs[4] = {v.x, v.y, v.z, v.w};
        ushort4 ph, pl;
        unsigned short* hp = &ph.x; unsigned short* lp = &pl.x;
#pragma unroll
        for (int i = 0; i < 4; i++) {
            __half h, l;
            split2(xs[i], h, l);
            hp[i] = __half_as_ushort(h);
            lp[i] = __half_as_ushort(l);
        }
        size_t o = (size_t)r * DD + tid * 4;
        *reinterpret_cast<ushort4*>(&g_A2[0][o]) = ph;
        *reinterpret_cast<ushort4*>(&g_A2[1][o]) = pl;
    } else {
        // ---- W split + transpose ([d][n] -> [col][k]), 64d x 32n tile ----
        // row stride 68 halves = 136 bytes: 8-byte aligned for ushort4 reads,
        // 2-way bank conflicts on the write phase (34 banks mod 32).
        __shared__ __half sh[2][32][68];
        int idx = bx - ROWS;               // 0..1023
        int c0 = (idx & 63) * 32;          // global col tile (0..2047)
        int d0 = (idx >> 6) * 64;          // d tile (0..960)
        int tx = tid & 31;
        int ty = tid >> 5;                 // 0..7
        const float* W = (c0 < NHQ) ? wq : wk;
        int nb = (c0 < NHQ) ? c0 : (c0 - NHQ);
#pragma unroll
        for (int i = 0; i < 8; i++) {
            int dl = ty + i * 8;           // 0..63
            float x = W[(size_t)(d0 + dl) * NHQ + nb + tx];
            __half h, l;
            split2(x, h, l);
            sh[0][tx][dl] = h;
            sh[1][tx][dl] = l;
        }
        __syncthreads();
#pragma unroll
        for (int j = 0; j < 2; j++) {
            int idx2 = tid + j * 256;      // 0..511
            int col = idx2 >> 4;           // 0..31
            int kq  = idx2 & 15;           // ushort4 chunk (4 k each)
            size_t o = (size_t)(c0 + col) * DD + d0 + kq * 4;
#pragma unroll
            for (int p = 0; p < 2; p++) {
                ushort4 v = *reinterpret_cast<const ushort4*>(&sh[p][col][kq * 4]);
                *reinterpret_cast<ushort4*>(&g_B2[p][o]) = v;
            }
        }
    }
}

// ---------------- GEMM: TMA + ldmatrix + mma.sync + fused logits partials ----------------
#define KC 64
#define NCHUNK (DD / KC)                 // 16
#define TILE_BYTES 16384                 // one 128x128B plane tile
#define STAGE_BYTES (4 * TILE_BYTES)     // A-hi, A-lo, B-hi, B-lo = 64 KB
#define NSTAGE 3
#define SMEM_TILES 1024
#define SMEM_TOTAL (SMEM_TILES + NSTAGE * STAGE_BYTES)   // 197632

__device__ __forceinline__ uint32_t smem_u32(const void* p) {
    uint32_t a;
    asm("{ .reg .u64 t; cvta.to.shared.u64 t, %1; cvt.u32.u64 %0, t; }" : "=r"(a) : "l"(p));
    return a;
}
#define MBAR_INIT(mb, n)  asm volatile("mbarrier.init.shared.b64 [%0], %1;" :: "r"((uint32_t)(mb)), "r"((uint32_t)(n)) : "memory")
#define MBAR_EXPECT_TX(mb, bytes) asm volatile("mbarrier.arrive.expect_tx.shared.b64 _, [%0], %1;" :: "r"((uint32_t)(mb)), "r"((uint32_t)(bytes)) : "memory")
#define MBAR_WAIT(mb, ph) do {                                                          \
    uint32_t _mb = (uint32_t)(mb); uint32_t _p = (uint32_t)(ph); uint32_t _done;        \
    asm volatile("{\n\t.reg .pred p;\n\t"                                               \
        "mbarrier.try_wait.parity.acquire.cta.shared::cta.b64 p, [%1], %2;\n\t"         \
        "selp.b32 %0, 1, 0, p;\n\t}" : "=r"(_done) : "r"(_mb), "r"(_p) : "memory");     \
    if (!_done) {                                                                       \
        asm volatile("{\n\t.reg .pred P1;\n\t"                                          \
            "WL_%=:\n\t"                                                                \
            "mbarrier.try_wait.parity.acquire.cta.shared::cta.b64 P1, [%0], %1, 0x989680;\n\t" \
            "@P1 bra.uni WD_%=;\n\t"                                                    \
            "bra.uni WL_%=;\n\t"                                                        \
            "WD_%=:\n\t}" :: "r"(_mb), "r"(_p) : "memory");                             \
    }                                                                                   \
} while (0)

#define TMA_LOAD_3D(sm, mp, x, y, z, mb)                                                \
    asm volatile("cp.async.bulk.tensor.3d.shared::cta.global.tile.mbarrier::complete_tx::bytes " \
        "[%0], [%1, {%2, %3, %4}], [%5];"                                               \
        :: "r"((uint32_t)(sm)), "l"(mp), "r"((int)(x)), "r"((int)(y)), "r"((int)(z)),   \
           "r"((uint32_t)(mb)) : "memory")

#define LDMATRIX_X4(r0, r1, r2, r3, a)                                                  \
    asm volatile("ldmatrix.sync.aligned.m8n8.x4.shared.b16 {%0,%1,%2,%3}, [%4];"        \
        : "=r"(r0), "=r"(r1), "=r"(r2), "=r"(r3) : "r"(a))
#define LDMATRIX_X2(r0, r1, a)                                                          \
    asm volatile("ldmatrix.sync.aligned.m8n8.x2.shared.b16 {%0,%1}, [%2];"              \
        : "=r"(r0), "=r"(r1) : "r"(a))

__device__ __forceinline__ void mma_f16(float* c, const uint32_t* a, const uint32_t* b) {
    asm volatile(
        "mma.sync.aligned.m16n8k16.row.col.f32.f16.f16.f32 "
        "{%0,%1,%2,%3}, {%4,%5,%6,%7}, {%8,%9}, {%0,%1,%2,%3};"
        : "+f"(c[0]), "+f"(c[1]), "+f"(c[2]), "+f"(c[3])
        : "r"(a[0]), "r"(a[1]), "r"(a[2]), "r"(a[3]), "r"(b[0]), "r"(b[1]));
}

// Grid (16, 8): blockIdx.x = 64-col range of BOTH Q and K; blockIdx.y = 128-row tile.
// B smem rows 0-63 = Q cols [c0, c0+64), rows 64-127 = K cols [c0, c0+64).
__global__ void __launch_bounds__(256, 1)
gemm_mma_kernel(const __grid_constant__ CUtensorMap tma_a,
                const __grid_constant__ CUtensorMap tma_b,
                const float* __restrict__ bq, const float* __restrict__ bk,
                const int* __restrict__ mask)
{
    extern __shared__ char smem[];
    const uint32_t sb = smem_u32(smem);

    const int tid = threadIdx.x;
    const int wid = tid >> 5, lane = tid & 31;
    const int g = lane >> 2, t = lane & 3;
    const int wr = wid >> 2;                  // 0..1 -> m offset wr*64
    const int wc = wid & 3;                   // 0..3 -> B rows wc*32 (wc<2: Q, wc>=2: K)
    const int tileR = blockIdx.y * 128;
    const int c0 = blockIdx.x * 64;           // col range within NHQ

    if (tid == 0) {
#pragma unroll
        for (int s = 0; s < NSTAGE; s++) MBAR_INIT(sb + s * 8, 1);
    }
    __syncthreads();
    if (tid == 0) {
#pragma unroll
        for (int s = 0; s < NSTAGE; s++) {
            uint32_t stg = sb + SMEM_TILES + s * STAGE_BYTES;
            MBAR_EXPECT_TX(sb + s * 8, STAGE_BYTES);
#pragma unroll
            for (int p = 0; p < 2; p++) {
                TMA_LOAD_3D(stg + p * TILE_BYTES, &tma_a, s * KC, tileR, p, sb + s * 8);
                uint32_t bt = stg + (2 + p) * TILE_BYTES;
                TMA_LOAD_3D(bt,        &tma_b, s * KC, c0,       p, sb + s * 8);  // Q cols -> rows 0-63
                TMA_LOAD_3D(bt + 8192, &tma_b, s * KC, NHQ + c0, p, sb + s * 8);  // K cols -> rows 64-127
            }
        }
    }

    // per-lane ldmatrix address components (swizzle xor depends only on lane&7)
    const int xr = (lane & 7) << 4;
    const int a_row_local = (lane & 7) + ((lane >> 3) & 1) * 8;
    const int a_kh16 = ((lane >> 4) & 1) * 16;
    const int b_row_local = lane & 7;
    const int b_kh16 = ((lane >> 3) & 1) * 16;

    uint32_t aro[4], bro[4];
#pragma unroll
    for (int mt = 0; mt < 4; mt++) aro[mt] = (uint32_t)(wr * 64 + mt * 16 + a_row_local) * 128;
#pragma unroll
    for (int nt = 0; nt < 4; nt++) bro[nt] = (uint32_t)(wc * 32 + nt * 8 + b_row_local) * 128;

    float acc0[4][4][4];
    float acc1[4][4][4];
#pragma unroll
    for (int i = 0; i < 4; i++)
#pragma unroll
        for (int j = 0; j < 4; j++)
#pragma unroll
            for (int r = 0; r < 4; r++) { acc0[i][j][r] = 0.f; acc1[i][j][r] = 0.f; }

    for (int c = 0; c < NCHUNK; c++) {
        const int s = c % NSTAGE;
        MBAR_WAIT(sb + s * 8, (c / NSTAGE) & 1);
        const uint32_t stg = sb + SMEM_TILES + (uint32_t)s * STAGE_BYTES;

#pragma unroll
        for (int ks = 0; ks < 4; ks++) {
            const uint32_t akt = (uint32_t)((ks * 32 + a_kh16) ^ xr);
            const uint32_t bkt = (uint32_t)((ks * 32 + b_kh16) ^ xr);
            uint32_t ah[4][4], al[4][4];
            uint32_t bh[4][2], bl[4][2];
#pragma unroll
            for (int mt = 0; mt < 4; mt++) {
                LDMATRIX_X4(ah[mt][0], ah[mt][1], ah[mt][2], ah[mt][3],
                            stg + 0 * TILE_BYTES + aro[mt] + akt);
                LDMATRIX_X4(al[mt][0], al[mt][1], al[mt][2], al[mt][3],
                            stg + 1 * TILE_BYTES + aro[mt] + akt);
            }
#pragma unroll
            for (int nt = 0; nt < 4; nt++) {
                LDMATRIX_X2(bh[nt][0], bh[nt][1], stg + 2 * TILE_BYTES + bro[nt] + bkt);
                LDMATRIX_X2(bl[nt][0], bl[nt][1], stg + 3 * TILE_BYTES + bro[nt] + bkt);
            }
#pragma unroll
            for (int mt = 0; mt < 4; mt++)
#pragma unroll
                for (int nt = 0; nt < 4; nt++) {
                    mma_f16(acc0[mt][nt], ah[mt], bh[nt]);
                    mma_f16(acc1[mt][nt], ah[mt], bl[nt]);
                    mma_f16(acc1[mt][nt], al[mt], bh[nt]);
                }
        }
        __syncthreads();
        if (c + NSTAGE < NCHUNK && tid == 0) {
            uint32_t dst = sb + SMEM_TILES + (uint32_t)s * STAGE_BYTES;
            MBAR_EXPECT_TX(sb + s * 8, STAGE_BYTES);
            int k0 = (c + NSTAGE) * KC;
#pragma unroll
            for (int p = 0; p < 2; p++) {
                TMA_LOAD_3D(dst + p * TILE_BYTES, &tma_a, k0, tileR, p, sb + s * 8);
                uint32_t bt = dst + (2 + p) * TILE_BYTES;
                TMA_LOAD_3D(bt,        &tma_b, k0, c0,       p, sb + s * 8);
                TMA_LOAD_3D(bt + 8192, &tma_b, k0, NHQ + c0, p, sb + s * 8);
            }
        }
    }

    // ---------------- epilogue: Q/K tiles to smem, ksum, CTA-local logit partials ----------------
    float* fsm = reinterpret_cast<float*>(smem);
    float* smQ = fsm;                 // [128][66]
    float* smK = fsm + 128 * 66;      // [128][66]
    float* smS = fsm + 2 * 128 * 66;  // [4][64] per-batch ksum

    const bool isK = (wc >= 2);
    const float* __restrict__ bias = isK ? bk : bq;
    float* dst = isK ? smK : smQ;

#pragma unroll
    for (int mt = 0; mt < 4; mt++) {
        int r0 = wr * 64 + mt * 16 + g;        // local row
        int r1 = r0 + 8;
        float m0 = (float)mask[tileR + r0];
        float m1 = (float)mask[tileR + r1];
#pragma unroll
        for (int nt = 0; nt < 4; nt++) {
            int cl = (wc & 1) * 32 + nt * 8 + t * 2;   // local col 0..62
            float b0 = bias[c0 + cl], b1 = bias[c0 + cl + 1];
            float v0 = acc0[mt][nt][0] + acc1[mt][nt][0] * LO_INV;
            float v1 = acc0[mt][nt][1] + acc1[mt][nt][1] * LO_INV;
            float v2 = acc0[mt][nt][2] + acc1[mt][nt][2] * LO_INV;
            float v3 = acc0[mt][nt][3] + acc1[mt][nt][3] * LO_INV;
            float2 o0, o1;
            o0.x = (v0 + b0) * m0;
            o0.y = (v1 + b1) * m0;
            o1.x = (v2 + b0) * m1;
            o1.y = (v3 + b1) * m1;
            *reinterpret_cast<float2*>(&dst[r0 * 66 + cl]) = o0;
            *reinterpret_cast<float2*>(&dst[r1 * 66 + cl]) = o1;
        }
    }
    __syncthreads();

    // per-batch ksum over local K tile (4 batches of 32 rows)
    {
        int batch = tid >> 6;          // 0..3
        int col   = tid & 63;          // 0..63
        float s = 0.f;
#pragma unroll
        for (int i = 0; i < 32; i++)
            s += smK[(batch * 32 + i) * 66 + col];
        smS[batch * 64 + col] = s;
    }
    __syncthreads();

    // logit partial per row: sum_c Q[x,c] * (ksum_b[c] - K[x,c])
    if (tid < 128) {
        int row = tid;
        int bl = row >> 5;
        float s = 0.f;
#pragma unroll
        for (int cc = 0; cc < 64; cc++)
            s += smQ[row * 66 + cc] * (smS[bl * 64 + cc] - smK[row * 66 + cc]);
        g_lpart[blockIdx.x * ROWS + tileR + row] = s;
    }
}

// ---------------- kernel 3: softmax (32 blocks x 32 threads) ----------------
__global__ void softmax_kernel(const int* __restrict__ mask, float* __restrict__ out)
{
    int b = blockIdx.x;
    int x = threadIdx.x;
    int row = b * AA + x;
    float l = 0.f;
#pragma unroll
    for (int ct = 0; ct < 16; ct++)
        l += g_lpart[ct * ROWS + row];
    float m = (float)mask[row];
    l += (1.0f - m) * -100000.0f;
    float mx = l;
#pragma unroll
    for (int o = 16; o > 0; o >>= 1) mx = fmaxf(mx, __shfl_xor_sync(0xffffffffu, mx, o));
    float e = expf(l - mx);
    float se = e;
#pragma unroll
    for (int o = 16; o > 0; o >>= 1) se += __shfl_xor_sync(0xffffffffu, se, o);
    out[row] = e / se;
}

// ---------------- host: tensor map construction ----------------
typedef CUresult (*EncodeTiledFn)(
    CUtensorMap*, CUtensorMapDataType, cuuint32_t, void*,
    const cuuint64_t*, const cuuint64_t*, const cuuint32_t*, const cuuint32_t*,
    CUtensorMapInterleave, CUtensorMapSwizzle, CUtensorMapL2promotion, CUtensorMapFloatOOBfill);

extern "C" void kernel_launch(void* const* d_in, const int* in_sizes, int n_in,
                              void* d_out, int out_size)
{
    const float* enc  = (const float*)d_in[0];
    const int*   mask = (const int*)  d_in[1];
    const float* wq   = (const float*)d_in[2];
    const float* bq   = (const float*)d_in[3];
    const float* wk   = (const float*)d_in[4];
    const float* bk   = (const float*)d_in[5];
    float* out = (float*)d_out;

    cudaFuncSetAttribute(gemm_mma_kernel, cudaFuncAttributeMaxDynamicSharedMemorySize, SMEM_TOTAL);

    void* fn = nullptr;
    cudaDriverEntryPointQueryResult qr;
    cudaGetDriverEntryPointByVersion("cuTensorMapEncodeTiled", &fn, 12000,
                                     cudaEnableDefault, &qr);
    EncodeTiledFn encode = (EncodeTiledFn)fn;

    void *pA = nullptr, *pB = nullptr;
    cudaGetSymbolAddress(&pA, g_A2);
    cudaGetSymbolAddress(&pB, g_B2);

    CUtensorMap tmaA, tmaB;
    {
        cuuint64_t dims[3]    = {DD, ROWS, 2};
        cuuint64_t strides[2] = {DD * 2ull, (cuuint64_t)ROWS * DD * 2ull};
        cuuint32_t box[3]     = {KC, 128, 1};
        cuuint32_t es[3]      = {1, 1, 1};
        encode(&tmaA, CU_TENSOR_MAP_DATA_TYPE_UINT16, 3, pA, dims, strides, box, es,
               CU_TENSOR_MAP_INTERLEAVE_NONE, CU_TENSOR_MAP_SWIZZLE_128B,
               CU_TENSOR_MAP_L2_PROMOTION_L2_128B, CU_TENSOR_MAP_FLOAT_OOB_FILL_NONE);
    }
    {
        cuuint64_t dims[3]    = {DD, COLS2, 2};
        cuuint64_t strides[2] = {DD * 2ull, (cuuint64_t)COLS2 * DD * 2ull};
        cuuint32_t box[3]     = {KC, 64, 1};
        cuuint32_t es[3]      = {1, 1, 1};
        encode(&tmaB, CU_TENSOR_MAP_DATA_TYPE_UINT16, 3, pB, dims, strides, box, es,
               CU_TENSOR_MAP_INTERLEAVE_NONE, CU_TENSOR_MAP_SWIZZLE_128B,
               CU_TENSOR_MAP_L2_PROMOTION_L2_128B, CU_TENSOR_MAP_FLOAT_OOB_FILL_NONE);
    }

    split_all_kernel<<<ROWS + 1024, 256>>>(enc, wq, wk);
    gemm_mma_kernel<<<dim3(16, 8), 256, SMEM_TOTAL>>>(tmaA, tmaB, bq, bk, mask);
    softmax_kernel<<<BB, 32>>>(mask, out);
}